// round 11
// baseline (speedup 1.0000x reference)
#include <cuda_runtime.h>
#include <math.h>

#define N_PART   16384
#define DDIM     16
#define PDIM     8
#define M_STEPS  50
#define HDIM     128
#define BLK_P    128
#define NTHREADS 256
#define LDIN     16        // sIn row stride (X only)
#define LDH      132       // sH / base row stride (132 mod 32 = 4 -> conflict-free)

typedef unsigned long long u64;

static __device__ __forceinline__ u64 fma2(u64 a, u64 b, u64 c) {
    u64 d;
    asm("fma.rn.f32x2 %0, %1, %2, %3;" : "=l"(d) : "l"(a), "l"(b), "l"(c));
    return d;
}
static __device__ __forceinline__ float2 unpack2(u64 v) {
    float2 f;
    asm("mov.b64 {%0, %1}, %2;" : "=f"(f.x), "=f"(f.y) : "l"(v));
    return f;
}
static __device__ __forceinline__ float hsum2(u64 v) {
    float2 f = unpack2(v);
    return f.x + f.y;
}

// k-pair GEMM tile: 8 rows (ty+16i) x 8 cols ({4tx..4tx+3} U {64+4tx..64+4tx+3}).
// Weights pre-interleaved: Wp[(k>>1)*256 + 2c + (k&1)] = W[k][c] -> the (even,odd)
// pair for one column is a single aligned u64; the A operand pair (a_k, a_k+1)
// is the free u64 view of the loaded float4. Zero pack/mov instructions.
// Accumulators hold (even-k partial, odd-k partial); caller sums the halves.
// Over-reads one Wp row and one A chunk past the end (caller keeps it in smem).
template <int K2, int LDA>
static __device__ __forceinline__ void mm_kp(const float* __restrict__ A,
                                             const float* __restrict__ Bp,
                                             u64 c[8][8]) {
    float4 a[8];
#pragma unroll
    for (int i = 0; i < 8; i++)
        a[i] = *(const float4*)(A + i * 16 * LDA);
    float4 b[4];
    b[0] = *(const float4*)(Bp + 0);
    b[1] = *(const float4*)(Bp + 4);
    b[2] = *(const float4*)(Bp + 128);
    b[3] = *(const float4*)(Bp + 132);

#pragma unroll 2
    for (int kp = 0; kp < K2; kp++) {
        u64 w0 = ((const u64*)&b[0])[0], w1 = ((const u64*)&b[0])[1];
        u64 w2 = ((const u64*)&b[1])[0], w3 = ((const u64*)&b[1])[1];
        u64 w4 = ((const u64*)&b[2])[0], w5 = ((const u64*)&b[2])[1];
        u64 w6 = ((const u64*)&b[3])[0], w7 = ((const u64*)&b[3])[1];
#pragma unroll
        for (int i = 0; i < 8; i++) {
            u64 a2 = ((const u64*)&a[i])[kp & 1];
            c[i][0] = fma2(a2, w0, c[i][0]);
            c[i][1] = fma2(a2, w1, c[i][1]);
            c[i][2] = fma2(a2, w2, c[i][2]);
            c[i][3] = fma2(a2, w3, c[i][3]);
            c[i][4] = fma2(a2, w4, c[i][4]);
            c[i][5] = fma2(a2, w5, c[i][5]);
            c[i][6] = fma2(a2, w6, c[i][6]);
            c[i][7] = fma2(a2, w7, c[i][7]);
        }
        // reload B for next kp (after last use; next-use distance = full kp body)
        const float* Bn = Bp + (size_t)(kp + 1) * 256;
        b[0] = *(const float4*)(Bn + 0);
        b[1] = *(const float4*)(Bn + 4);
        b[2] = *(const float4*)(Bn + 128);
        b[3] = *(const float4*)(Bn + 132);
        if (kp & 1) {   // reload A chunk for next 2 k-pairs
#pragma unroll
            for (int i = 0; i < 8; i++)
                a[i] = *(const float4*)(A + i * 16 * LDA + 4 * ((kp >> 1) + 1));
        }
    }
}

__global__ void __launch_bounds__(NTHREADS, 1)
sde_rollout_kernel(const float* __restrict__ X0, const float* __restrict__ V0,
                   const float* __restrict__ obs, const float* __restrict__ noise,
                   const float* __restrict__ W1, const float* __restrict__ b1,
                   const float* __restrict__ W2, const float* __restrict__ b2,
                   const float* __restrict__ W3, const float* __restrict__ b3,
                   float* __restrict__ out) {
    extern __shared__ float sm[];
    float* W1xp = sm;                       // 8*256  = 2048  (pair-interleaved W1 X-rows)
    float* w1ts = W1xp + 2048;              // 128            (W1 t-row)
    float* b1s  = w1ts + HDIM;              // 128
    float* W2p  = b1s + HDIM;               // 64*256 = 16384 (pair-interleaved)
    float* b2s  = W2p + 16384;              // 128
    float* W3p  = b2s + HDIM;               // 64*32  = 2048  (pair-interleaved)
    float* b3s  = W3p + 2048;               // 16
    float* sIn  = b3s + 16;                 // 128*16 = 2048  (X state)
    float* sH   = sIn + BLK_P * LDIN;       // 128*132 = 16896
    float* sV   = sH + BLK_P * LDH;         // 128
    float* base = sV + BLK_P;               // 128*132 = 16896 (obs@W1o + b1)
    // total = 56848 floats = 227392 B

    const int tid = threadIdx.x;
    const int pbase = blockIdx.x * BLK_P;

    // ---- cooperative weight load (pair-interleave on the fly) ----
    for (int s = tid; s < 16 * HDIM; s += NTHREADS) {
        int k = s >> 7, cc = s & 127;
        W1xp[(k >> 1) * 256 + 2 * cc + (k & 1)] = W1[(1 + k) * HDIM + cc];
    }
    for (int s = tid; s < HDIM * HDIM; s += NTHREADS) {
        int k = s >> 7, cc = s & 127;
        W2p[(k >> 1) * 256 + 2 * cc + (k & 1)] = W2[s];
    }
    for (int s = tid; s < HDIM * DDIM; s += NTHREADS) {
        int k = s >> 4, cc = s & 15;
        W3p[(k >> 1) * 32 + 2 * cc + (k & 1)] = W3[s];
    }
    if (tid < HDIM) { w1ts[tid] = W1[tid]; b1s[tid] = b1[tid]; b2s[tid] = b2[tid]; }
    if (tid < DDIM) b3s[tid] = b3[tid];
    // W1 obs rows (17..24) -> scratch in base rows 0..7
    for (int s = tid; s < PDIM * HDIM; s += NTHREADS) {
        int k = s >> 7, cc = s & 127;
        base[k * LDH + cc] = W1[(17 + k) * HDIM + cc];
    }

    // ---- init particle state ----
    const int p  = tid >> 1;
    const int dh = (tid & 1) * 8;
    const int pg = pbase + p;
    {
        float4 xa = *(const float4*)(X0 + (size_t)pg * DDIM + dh);
        float4 xb = *(const float4*)(X0 + (size_t)pg * DDIM + dh + 4);
        *(float4*)(sIn + p * LDIN + dh)     = xa;
        *(float4*)(sIn + p * LDIN + dh + 4) = xb;
        if ((tid & 1) == 0) {
            sV[p] = V0[pg];
#pragma unroll
            for (int j = 0; j < PDIM; j++)
                sH[p * LDH + j] = obs[(size_t)pg * PDIM + j];   // obs scratch
        }
    }
    __syncthreads();

    const int ty = tid >> 4, tx = tid & 15;

    // ---- base = obs @ W1o + b1 (one-time K=8 GEMM, naive) ----
    {
        float acc[8][8];
#pragma unroll
        for (int i = 0; i < 8; i++)
#pragma unroll
            for (int j = 0; j < 8; j++) acc[i][j] = 0.0f;
        for (int k = 0; k < PDIM; k++) {
            float w[8];
#pragma unroll
            for (int j = 0; j < 4; j++) {
                w[j]     = base[k * LDH + 4 * tx + j];
                w[4 + j] = base[k * LDH + 64 + 4 * tx + j];
            }
#pragma unroll
            for (int i = 0; i < 8; i++) {
                float o = sH[(ty + 16 * i) * LDH + k];
#pragma unroll
                for (int j = 0; j < 8; j++)
                    acc[i][j] = fmaf(o, w[j], acc[i][j]);
            }
        }
        __syncthreads();    // all W1o reads done before base is overwritten
        float4 c0 = *(const float4*)(b1s + 4 * tx);
        float4 c1 = *(const float4*)(b1s + 64 + 4 * tx);
#pragma unroll
        for (int i = 0; i < 8; i++) {
            int row = ty + 16 * i;
            float4 o0 = { acc[i][0] + c0.x, acc[i][1] + c0.y,
                          acc[i][2] + c0.z, acc[i][3] + c0.w };
            float4 o1 = { acc[i][4] + c1.x, acc[i][5] + c1.y,
                          acc[i][6] + c1.z, acc[i][7] + c1.w };
            *(float4*)(base + row * LDH + 4 * tx) = o0;
            *(float4*)(base + row * LDH + 64 + 4 * tx) = o1;
        }
    }
    __syncthreads();

    const float dt   = (float)(1.0 / (double)M_STEPS);  // T = 1
    const float sqdt = sqrtf(dt);

    // loop-invariant fragments -> registers
    const float4 b2A = *(const float4*)(b2s + 4 * tx);
    const float4 b2B = *(const float4*)(b2s + 64 + 4 * tx);
    const float4 b3a = *(const float4*)(b3s + dh);
    const float4 b3b = *(const float4*)(b3s + dh + 4);
    const float4 w1A = *(const float4*)(w1ts + 4 * tx);
    const float4 w1B = *(const float4*)(w1ts + 64 + 4 * tx);

    for (int m = 0; m < M_STEPS; m++) {
        const float t = (float)m * dt;
        float tw[8] = { t * w1A.x, t * w1A.y, t * w1A.z, t * w1A.w,
                        t * w1B.x, t * w1B.y, t * w1B.z, t * w1B.w };

        // ---- layer 1: h1 = relu(X@W1x + t*W1t + base), K=16 -> 8 k-pairs ----
        u64 c[8][8];
#pragma unroll
        for (int i = 0; i < 8; i++)
#pragma unroll
            for (int j = 0; j < 8; j++) c[i][j] = 0ull;
        mm_kp<8, LDIN>(sIn + ty * LDIN, W1xp + 8 * tx, c);
#pragma unroll
        for (int i = 0; i < 8; i++) {
            int row = ty + 16 * i;
            float4 bb0 = *(const float4*)(base + row * LDH + 4 * tx);
            float4 bb1 = *(const float4*)(base + row * LDH + 64 + 4 * tx);
            float4 o0 = { fmaxf(hsum2(c[i][0]) + bb0.x + tw[0], 0.0f),
                          fmaxf(hsum2(c[i][1]) + bb0.y + tw[1], 0.0f),
                          fmaxf(hsum2(c[i][2]) + bb0.z + tw[2], 0.0f),
                          fmaxf(hsum2(c[i][3]) + bb0.w + tw[3], 0.0f) };
            float4 o1 = { fmaxf(hsum2(c[i][4]) + bb1.x + tw[4], 0.0f),
                          fmaxf(hsum2(c[i][5]) + bb1.y + tw[5], 0.0f),
                          fmaxf(hsum2(c[i][6]) + bb1.z + tw[6], 0.0f),
                          fmaxf(hsum2(c[i][7]) + bb1.w + tw[7], 0.0f) };
            *(float4*)(sH + row * LDH + 4 * tx) = o0;
            *(float4*)(sH + row * LDH + 64 + 4 * tx) = o1;
        }
        __syncthreads();

        // ---- layer 2: h2 = relu(h1 @ W2 + b2), 64 k-pairs ----
#pragma unroll
        for (int i = 0; i < 8; i++)
#pragma unroll
            for (int j = 0; j < 8; j++) c[i][j] = 0ull;
        mm_kp<64, LDH>(sH + ty * LDH, W2p + 8 * tx, c);

        // prefetch this step's noise (hides behind syncs + layer 3)
        const float* np = noise + (((size_t)m * N_PART + pg) * DDIM + dh);
        float4 e0 = *(const float4*)np;
        float4 e1 = *(const float4*)(np + 4);

        __syncthreads();                        // everyone done reading h1
#pragma unroll
        for (int i = 0; i < 8; i++) {
            int row = ty + 16 * i;
            float4 o0 = { fmaxf(hsum2(c[i][0]) + b2A.x, 0.0f),
                          fmaxf(hsum2(c[i][1]) + b2A.y, 0.0f),
                          fmaxf(hsum2(c[i][2]) + b2A.z, 0.0f),
                          fmaxf(hsum2(c[i][3]) + b2A.w, 0.0f) };
            float4 o1 = { fmaxf(hsum2(c[i][4]) + b2B.x, 0.0f),
                          fmaxf(hsum2(c[i][5]) + b2B.y, 0.0f),
                          fmaxf(hsum2(c[i][6]) + b2B.z, 0.0f),
                          fmaxf(hsum2(c[i][7]) + b2B.w, 0.0f) };
            *(float4*)(sH + row * LDH + 4 * tx) = o0;
            *(float4*)(sH + row * LDH + 64 + 4 * tx) = o1;
        }
        __syncthreads();

        // ---- layer 3: Z = h2 @ W3 + b3 (2 threads/particle, k-paired) ----
        u64 cz[8];
#pragma unroll
        for (int j = 0; j < 8; j++) cz[j] = 0ull;
        const float* hrow = sH + p * LDH;
        const float* w3r = W3p + 2 * dh;
        float4 hv = *(const float4*)(hrow);
#pragma unroll 4
        for (int kp = 0; kp < 64; kp++) {
            u64 a2 = ((const u64*)&hv)[kp & 1];
            const float* wr = w3r + kp * 32;
            float4 v0 = *(const float4*)(wr);
            float4 v1 = *(const float4*)(wr + 4);
            float4 v2 = *(const float4*)(wr + 8);
            float4 v3 = *(const float4*)(wr + 12);
            cz[0] = fma2(a2, ((const u64*)&v0)[0], cz[0]);
            cz[1] = fma2(a2, ((const u64*)&v0)[1], cz[1]);
            cz[2] = fma2(a2, ((const u64*)&v1)[0], cz[2]);
            cz[3] = fma2(a2, ((const u64*)&v1)[1], cz[3]);
            cz[4] = fma2(a2, ((const u64*)&v2)[0], cz[4]);
            cz[5] = fma2(a2, ((const u64*)&v2)[1], cz[5]);
            cz[6] = fma2(a2, ((const u64*)&v3)[0], cz[6]);
            cz[7] = fma2(a2, ((const u64*)&v3)[1], cz[7]);
            if (kp & 1) hv = *(const float4*)(hrow + 2 * (kp + 1));
        }
        const float* b3f = (const float*)&b3a;
        const float* b3g = (const float*)&b3b;
        float z[8];
#pragma unroll
        for (int j = 0; j < 4; j++) {
            z[j]     = hsum2(cz[j])     + b3f[j];
            z[4 + j] = hsum2(cz[4 + j]) + b3g[j];
        }
        float eps[8] = {e0.x, e0.y, e0.z, e0.w, e1.x, e1.y, e1.z, e1.w};

        float zz = 0.0f, zw = 0.0f;
#pragma unroll
        for (int j = 0; j < 8; j++) {
            zz = fmaf(z[j], z[j], zz);
            zw = fmaf(z[j], sqdt * eps[j], zw);
        }
        zz += __shfl_xor_sync(0xffffffffu, zz, 1);
        zw += __shfl_xor_sync(0xffffffffu, zw, 1);

        // X <- X*(1-dt) + sqrt(dt)*eps   (sigma = 1)
        float* xr = sIn + p * LDIN + dh;
        float4 xv0 = *(const float4*)xr;
        float4 xv1 = *(const float4*)(xr + 4);
        xv0.x = fmaf(xv0.x, 1.0f - dt, sqdt * eps[0]);
        xv0.y = fmaf(xv0.y, 1.0f - dt, sqdt * eps[1]);
        xv0.z = fmaf(xv0.z, 1.0f - dt, sqdt * eps[2]);
        xv0.w = fmaf(xv0.w, 1.0f - dt, sqdt * eps[3]);
        xv1.x = fmaf(xv1.x, 1.0f - dt, sqdt * eps[4]);
        xv1.y = fmaf(xv1.y, 1.0f - dt, sqdt * eps[5]);
        xv1.z = fmaf(xv1.z, 1.0f - dt, sqdt * eps[6]);
        xv1.w = fmaf(xv1.w, 1.0f - dt, sqdt * eps[7]);
        *(float4*)xr = xv0;
        *(float4*)(xr + 4) = xv1;

        if ((tid & 1) == 0)
            sV[p] = sV[p] + dt * 0.5f * zz + zw;     // V update
        __syncthreads();
    }

    // ---- write outputs: X (N*16) then V (N) ----
    {
        float* xo = out + (size_t)pg * DDIM + dh;
        const float* xr = sIn + p * LDIN + dh;
        *(float4*)xo = *(const float4*)xr;
        *(float4*)(xo + 4) = *(const float4*)(xr + 4);
        if ((tid & 1) == 0) out[(size_t)N_PART * DDIM + pg] = sV[p];
    }
}

extern "C" void kernel_launch(void* const* d_in, const int* in_sizes, int n_in,
                              void* d_out, int out_size) {
    const float* X0    = (const float*)d_in[0];
    const float* V0    = (const float*)d_in[1];
    const float* obs   = (const float*)d_in[2];
    const float* noise = (const float*)d_in[3];
    const float* W1    = (const float*)d_in[4];
    const float* b1    = (const float*)d_in[5];
    const float* W2    = (const float*)d_in[6];
    const float* b2    = (const float*)d_in[7];
    const float* W3    = (const float*)d_in[8];
    const float* b3    = (const float*)d_in[9];
    float* out = (float*)d_out;

    const size_t smem_bytes = (size_t)56848 * sizeof(float);   // 227392 B

    cudaFuncSetAttribute(sde_rollout_kernel,
                         cudaFuncAttributeMaxDynamicSharedMemorySize,
                         (int)smem_bytes);

    sde_rollout_kernel<<<N_PART / BLK_P, NTHREADS, smem_bytes>>>(
        X0, V0, obs, noise, W1, b1, W2, b2, W3, b3, out);
}

// round 12
// speedup vs baseline: 1.0184x; 1.0184x over previous
#include <cuda_runtime.h>
#include <math.h>

#define N_PART   16384
#define DDIM     16
#define PDIM     8
#define M_STEPS  50
#define HDIM     128
#define BLK_P    128
#define NTHREADS 512
#define LDIN     16        // sIn row stride (X only)
#define LDH      132       // sH / base row stride (132 mod 32 = 4 -> conflict-free)

typedef unsigned long long u64;

static __device__ __forceinline__ u64 pack2(float x, float y) {
    u64 r;
    asm("mov.b64 %0, {%1, %2};" : "=l"(r) : "f"(x), "f"(y));
    return r;
}
static __device__ __forceinline__ u64 fma2(u64 a, u64 b, u64 c) {
    u64 d;
    asm("fma.rn.f32x2 %0, %1, %2, %3;" : "=l"(d) : "l"(a), "l"(b), "l"(c));
    return d;
}
static __device__ __forceinline__ float2 unpack2(u64 v) {
    float2 f;
    asm("mov.b64 {%0, %1}, %2;" : "=f"(f.x), "=f"(f.y) : "l"(v));
    return f;
}

// C tile: 4 rows (ty + 32*i) x 8 cols ({4tx..4tx+3} U {64+4tx..64+4tx+3}).
// ty in [0,32), tx in [0,16). A rows at stride 32*LDA, k-chunks of 4 as float4
// (two ty rows per warp are LDA*... words apart; LDH mod 32 = 4 -> conflict-free).
// B: per k, two float4 at [k*LDB+4tx] and [k*LDB+64+4tx] (contiguous -> LDS.128,
// conflict-free), prefetched one k ahead. Over-reads one B row past the end and
// one A chunk past K (caller guarantees those bytes are inside smem).
template <int K4, int LDA, int LDB>
static __device__ __forceinline__ void mm_tile4(const float* __restrict__ A,
                                                const float* __restrict__ B,
                                                u64 c[4][4]) {
    float4 bA = *(const float4*)(B);
    float4 bB = *(const float4*)(B + 64);

#pragma unroll 2
    for (int kk = 0; kk < K4; kk++) {
        float4 a[4];
#pragma unroll
        for (int i = 0; i < 4; i++)
            a[i] = *(const float4*)(A + i * 32 * LDA + 4 * kk);
#pragma unroll
        for (int j = 0; j < 4; j++) {
            const int k = 4 * kk + j;
            float4 nA = *(const float4*)(B + (size_t)(k + 1) * LDB);
            float4 nB = *(const float4*)(B + (size_t)(k + 1) * LDB + 64);
            const u64* bAp = (const u64*)&bA;
            const u64* bBp = (const u64*)&bB;
            u64 b0 = bAp[0], b1 = bAp[1], b2 = bBp[0], b3 = bBp[1];
#pragma unroll
            for (int i = 0; i < 4; i++) {
                const float* af = (const float*)&a[i];
                float av = af[j];
                u64 a2 = pack2(av, av);
                c[i][0] = fma2(a2, b0, c[i][0]);
                c[i][1] = fma2(a2, b1, c[i][1]);
                c[i][2] = fma2(a2, b2, c[i][2]);
                c[i][3] = fma2(a2, b3, c[i][3]);
            }
            bA = nA; bB = nB;
        }
    }
}

// relu(c + bias) -> dst  (rows ty+32i, col groups 4tx and 64+4tx)
static __device__ __forceinline__ void store_relu_bias(float* __restrict__ dst,
                                                       int ty, int tx,
                                                       const u64 c[4][4],
                                                       float4 biasA, float4 biasB) {
#pragma unroll
    for (int i = 0; i < 4; i++) {
        float* drow = dst + (ty + 32 * i) * LDH;
        float2 v0 = unpack2(c[i][0]);
        float2 v1 = unpack2(c[i][1]);
        float4 o;
        o.x = fmaxf(v0.x + biasA.x, 0.0f);
        o.y = fmaxf(v0.y + biasA.y, 0.0f);
        o.z = fmaxf(v1.x + biasA.z, 0.0f);
        o.w = fmaxf(v1.y + biasA.w, 0.0f);
        *(float4*)(drow + 4 * tx) = o;
        float2 w0 = unpack2(c[i][2]);
        float2 w1 = unpack2(c[i][3]);
        float4 q;
        q.x = fmaxf(w0.x + biasB.x, 0.0f);
        q.y = fmaxf(w0.y + biasB.y, 0.0f);
        q.z = fmaxf(w1.x + biasB.z, 0.0f);
        q.w = fmaxf(w1.y + biasB.w, 0.0f);
        *(float4*)(drow + 64 + 4 * tx) = q;
    }
}

static __device__ __forceinline__ void store_relu(float* __restrict__ dst,
                                                  int ty, int tx,
                                                  const u64 c[4][4]) {
#pragma unroll
    for (int i = 0; i < 4; i++) {
        float* drow = dst + (ty + 32 * i) * LDH;
        float2 v0 = unpack2(c[i][0]);
        float2 v1 = unpack2(c[i][1]);
        float4 o;
        o.x = fmaxf(v0.x, 0.0f); o.y = fmaxf(v0.y, 0.0f);
        o.z = fmaxf(v1.x, 0.0f); o.w = fmaxf(v1.y, 0.0f);
        *(float4*)(drow + 4 * tx) = o;
        float2 w0 = unpack2(c[i][2]);
        float2 w1 = unpack2(c[i][3]);
        float4 q;
        q.x = fmaxf(w0.x, 0.0f); q.y = fmaxf(w0.y, 0.0f);
        q.z = fmaxf(w1.x, 0.0f); q.w = fmaxf(w1.y, 0.0f);
        *(float4*)(drow + 64 + 4 * tx) = q;
    }
}

__global__ void __launch_bounds__(NTHREADS, 1)
sde_rollout_kernel(const float* __restrict__ X0, const float* __restrict__ V0,
                   const float* __restrict__ obs, const float* __restrict__ noise,
                   const float* __restrict__ W1, const float* __restrict__ b1,
                   const float* __restrict__ W2, const float* __restrict__ b2,
                   const float* __restrict__ W3, const float* __restrict__ b3,
                   float* __restrict__ out) {
    extern __shared__ float sm[];
    float* W1xs = sm;                       // 16*128 = 2048  (W1 rows 1..16: X part)
    float* w1ts = W1xs + 16 * HDIM;         // 128            (W1 row 0: t part)
    float* b1s  = w1ts + HDIM;              // 128
    float* W2s  = b1s + HDIM;               // 128*128 = 16384
    float* b2s  = W2s + HDIM * HDIM;        // 128
    float* W3s  = b2s + HDIM;               // 128*16 = 2048
    float* b3s  = W3s + HDIM * DDIM;        // 16
    float* sIn  = b3s + 16;                 // 128*16 = 2048  (X state)
    float* sH   = sIn + BLK_P * LDIN;       // 128*132 = 16896
    float* sV   = sH + BLK_P * LDH;         // 128
    float* base = sV + BLK_P;               // 128*132 = 16896 (obs@W1o + b1)
    // total = 56848 floats = 227392 B

    const int tid = threadIdx.x;
    const int pbase = blockIdx.x * BLK_P;

    // ---- cooperative weight load ----
    for (int i = tid; i < (16 * HDIM) / 4; i += NTHREADS)
        ((float4*)W1xs)[i] = ((const float4*)(W1 + HDIM))[i];       // rows 1..16
    for (int i = tid; i < (HDIM * HDIM) / 4; i += NTHREADS)
        ((float4*)W2s)[i] = ((const float4*)W2)[i];
    for (int i = tid; i < (HDIM * DDIM) / 4; i += NTHREADS)
        ((float4*)W3s)[i] = ((const float4*)W3)[i];
    if (tid < HDIM) {
        w1ts[tid] = W1[tid];                                        // row 0
        b1s[tid] = b1[tid];
        b2s[tid] = b2[tid];
    }
    if (tid < DDIM) b3s[tid] = b3[tid];
    // W1 obs rows (17..24) -> scratch: base rows 0..7
    for (int s = tid; s < PDIM * HDIM; s += NTHREADS) {
        int k = s >> 7, cc = s & 127;
        base[k * LDH + cc] = W1[(17 + k) * HDIM + cc];
    }

    // ---- init particle state (4 threads per particle, 4 dims each) ----
    const int p  = tid >> 2;
    const int dq = (tid & 3) * 4;
    const int pg = pbase + p;
    {
        float4 xa = *(const float4*)(X0 + (size_t)pg * DDIM + dq);
        *(float4*)(sIn + p * LDIN + dq) = xa;
        if ((tid & 3) == 0) {
            sV[p] = V0[pg];
#pragma unroll
            for (int j = 0; j < PDIM; j++)
                sH[p * LDH + j] = obs[(size_t)pg * PDIM + j];       // obs scratch
        }
    }
    __syncthreads();

    const int ty = tid >> 4, tx = tid & 15;

    // ---- base = obs @ W1o + b1 (one-time K=8 GEMM) ----
    {
        float acc[4][8];
#pragma unroll
        for (int i = 0; i < 4; i++)
#pragma unroll
            for (int j = 0; j < 8; j++) acc[i][j] = 0.0f;
        for (int k = 0; k < PDIM; k++) {
            float w[8];
#pragma unroll
            for (int j = 0; j < 4; j++) {
                w[j]     = base[k * LDH + 4 * tx + j];
                w[4 + j] = base[k * LDH + 64 + 4 * tx + j];
            }
#pragma unroll
            for (int i = 0; i < 4; i++) {
                float o = sH[(ty + 32 * i) * LDH + k];
#pragma unroll
                for (int j = 0; j < 8; j++)
                    acc[i][j] = fmaf(o, w[j], acc[i][j]);
            }
        }
        __syncthreads();    // all W1o reads done before base is overwritten
        float4 c0 = *(const float4*)(b1s + 4 * tx);
        float4 c1 = *(const float4*)(b1s + 64 + 4 * tx);
#pragma unroll
        for (int i = 0; i < 4; i++) {
            int row = ty + 32 * i;
            float4 o0 = { acc[i][0] + c0.x, acc[i][1] + c0.y,
                          acc[i][2] + c0.z, acc[i][3] + c0.w };
            float4 o1 = { acc[i][4] + c1.x, acc[i][5] + c1.y,
                          acc[i][6] + c1.z, acc[i][7] + c1.w };
            *(float4*)(base + row * LDH + 4 * tx) = o0;
            *(float4*)(base + row * LDH + 64 + 4 * tx) = o1;
        }
    }
    __syncthreads();

    const float dt   = (float)(1.0 / (double)M_STEPS);  // T = 1
    const float sqdt = sqrtf(dt);

    // loop-invariant fragments -> registers
    const float4 b2A = *(const float4*)(b2s + 4 * tx);
    const float4 b2B = *(const float4*)(b2s + 64 + 4 * tx);
    const float4 b3q = *(const float4*)(b3s + dq);
    const float4 w1A = *(const float4*)(w1ts + 4 * tx);
    const float4 w1B = *(const float4*)(w1ts + 64 + 4 * tx);

    for (int m = 0; m < M_STEPS; m++) {
        const float t = (float)m * dt;
        float tw[8] = { t * w1A.x, t * w1A.y, t * w1A.z, t * w1A.w,
                        t * w1B.x, t * w1B.y, t * w1B.z, t * w1B.w };

        // ---- layer 1: h1 = relu(X@W1x + t*W1t + base), K=16 ----
        u64 c[4][4];
#pragma unroll
        for (int i = 0; i < 4; i++) {
            const float* brow = base + (ty + 32 * i) * LDH;
            float4 fA = *(const float4*)(brow + 4 * tx);
            float4 fB = *(const float4*)(brow + 64 + 4 * tx);
            c[i][0] = pack2(fA.x + tw[0], fA.y + tw[1]);
            c[i][1] = pack2(fA.z + tw[2], fA.w + tw[3]);
            c[i][2] = pack2(fB.x + tw[4], fB.y + tw[5]);
            c[i][3] = pack2(fB.z + tw[6], fB.w + tw[7]);
        }
        mm_tile4<4, LDIN, HDIM>(sIn + ty * LDIN, W1xs + 4 * tx, c);
        store_relu(sH, ty, tx, c);
        __syncthreads();

        // ---- layer 2: h2 = relu(h1 @ W2 + b2) ----
#pragma unroll
        for (int i = 0; i < 4; i++) { c[i][0]=0; c[i][1]=0; c[i][2]=0; c[i][3]=0; }
        mm_tile4<HDIM / 4, LDH, HDIM>(sH + ty * LDH, W2s + 4 * tx, c);

        // prefetch this step's noise (hides behind syncs + layer 3)
        const float* np = noise + (((size_t)m * N_PART + pg) * DDIM + dq);
        float4 ev = *(const float4*)np;

        __syncthreads();                            // everyone done reading h1
        store_relu_bias(sH, ty, tx, c, b2A, b2B);
        __syncthreads();

        // ---- layer 3: Z = h2 @ W3 + b3 (4 threads/particle, 4 dims each) ----
        u64 cz[2] = {0, 0};
        const float* hrow = sH + p * LDH;
#pragma unroll 4
        for (int kk = 0; kk < HDIM / 4; kk++) {
            float4 hv = *(const float4*)(hrow + 4 * kk);
            const float* hf = (const float*)&hv;
#pragma unroll
            for (int j = 0; j < 4; j++) {
                const int k = 4 * kk + j;
                u64 a2 = pack2(hf[j], hf[j]);
                ulonglong2 w01 = *(const ulonglong2*)(W3s + k * DDIM + dq);
                cz[0] = fma2(a2, w01.x, cz[0]);
                cz[1] = fma2(a2, w01.y, cz[1]);
            }
        }
        const float* b3f = (const float*)&b3q;
        float z[4];
        {
            float2 v0 = unpack2(cz[0]), v1 = unpack2(cz[1]);
            z[0] = v0.x + b3f[0]; z[1] = v0.y + b3f[1];
            z[2] = v1.x + b3f[2]; z[3] = v1.y + b3f[3];
        }
        float eps[4] = {ev.x, ev.y, ev.z, ev.w};

        float zz = 0.0f, zw = 0.0f;
#pragma unroll
        for (int j = 0; j < 4; j++) {
            zz = fmaf(z[j], z[j], zz);
            zw = fmaf(z[j], sqdt * eps[j], zw);
        }
        zz += __shfl_xor_sync(0xffffffffu, zz, 1);
        zw += __shfl_xor_sync(0xffffffffu, zw, 1);
        zz += __shfl_xor_sync(0xffffffffu, zz, 2);
        zw += __shfl_xor_sync(0xffffffffu, zw, 2);

        // X <- X*(1-dt) + sqrt(dt)*eps   (sigma = 1)
        float* xr = sIn + p * LDIN + dq;
        float4 xv = *(const float4*)xr;
        xv.x = fmaf(xv.x, 1.0f - dt, sqdt * eps[0]);
        xv.y = fmaf(xv.y, 1.0f - dt, sqdt * eps[1]);
        xv.z = fmaf(xv.z, 1.0f - dt, sqdt * eps[2]);
        xv.w = fmaf(xv.w, 1.0f - dt, sqdt * eps[3]);
        *(float4*)xr = xv;

        if ((tid & 3) == 0)
            sV[p] = sV[p] + dt * 0.5f * zz + zw;     // V update
        __syncthreads();
    }

    // ---- write outputs: X (N*16) then V (N) ----
    {
        float* xo = out + (size_t)pg * DDIM + dq;
        *(float4*)xo = *(const float4*)(sIn + p * LDIN + dq);
        if ((tid & 3) == 0) out[(size_t)N_PART * DDIM + pg] = sV[p];
    }
}

extern "C" void kernel_launch(void* const* d_in, const int* in_sizes, int n_in,
                              void* d_out, int out_size) {
    const float* X0    = (const float*)d_in[0];
    const float* V0    = (const float*)d_in[1];
    const float* obs   = (const float*)d_in[2];
    const float* noise = (const float*)d_in[3];
    const float* W1    = (const float*)d_in[4];
    const float* b1    = (const float*)d_in[5];
    const float* W2    = (const float*)d_in[6];
    const float* b2    = (const float*)d_in[7];
    const float* W3    = (const float*)d_in[8];
    const float* b3    = (const float*)d_in[9];
    float* out = (float*)d_out;

    const size_t smem_bytes = (size_t)56848 * sizeof(float);   // 227392 B

    cudaFuncSetAttribute(sde_rollout_kernel,
                         cudaFuncAttributeMaxDynamicSharedMemorySize,
                         (int)smem_bytes);

    sde_rollout_kernel<<<N_PART / BLK_P, NTHREADS, smem_bytes>>>(
        X0, V0, obs, noise, W1, b1, W2, b2, W3, b3, out);
}

// round 13
// speedup vs baseline: 1.1051x; 1.0852x over previous
#include <cuda_runtime.h>
#include <math.h>

#define N_PART   16384
#define DDIM     16
#define PDIM     8
#define M_STEPS  50
#define HDIM     128
#define BLK_P    128
#define NTHREADS 256
#define LDIN     16        // sIn row stride (X only)
#define LDH      132       // sH / base row stride (132 mod 32 = 4 -> conflict-free)

typedef unsigned long long u64;

static __device__ __forceinline__ u64 pack2(float x, float y) {
    u64 r;
    asm("mov.b64 %0, {%1, %2};" : "=l"(r) : "f"(x), "f"(y));
    return r;
}
static __device__ __forceinline__ u64 fma2(u64 a, u64 b, u64 c) {
    u64 d;
    asm("fma.rn.f32x2 %0, %1, %2, %3;" : "=l"(d) : "l"(a), "l"(b), "l"(c));
    return d;
}
static __device__ __forceinline__ float2 unpack2(u64 v) {
    float2 f;
    asm("mov.b64 {%0, %1}, %2;" : "=f"(f.x), "=f"(f.y) : "l"(v));
    return f;
}

// C tile: 8 rows (rg + 16*i) x 8 consecutive cols (cb..cb+7), cb = 16*wid + 8*cgg.
// Warp w covers cols [16w, 16w+16) only -> its per-k B fragment is 64 unique
// bytes (2x LDS.128 with 2 distinct addresses each: broadcast, ~1 wavefront)
// instead of the full 512B row. A loads are lane-broadcast (address depends on
// rg only; rg stride LDH=132 words == 4 mod 32 -> conflict-free phases).
// B prefetched one k ahead; A chunk (float4 = 4 k's) reloaded each 4 k.
// Over-reads one B row and one A chunk past the end (stays inside smem).
template <int K4, int LDA, int LDB>
static __device__ __forceinline__ void mm_tile_v(const float* __restrict__ A,
                                                 const float* __restrict__ B,
                                                 u64 c[8][4]) {
    float4 a[8];
#pragma unroll
    for (int i = 0; i < 8; i++)
        a[i] = *(const float4*)(A + i * 16 * LDA);
    float4 bA = *(const float4*)(B);
    float4 bB = *(const float4*)(B + 4);

#pragma unroll 2
    for (int kk = 0; kk < K4; kk++) {
#pragma unroll
        for (int j = 0; j < 4; j++) {
            const int k = 4 * kk + j;
            float4 nA = *(const float4*)(B + (size_t)(k + 1) * LDB);
            float4 nB = *(const float4*)(B + (size_t)(k + 1) * LDB + 4);
            float4 an[8];
            if (j == 3) {
#pragma unroll
                for (int i = 0; i < 8; i++)
                    an[i] = *(const float4*)(A + i * 16 * LDA + 4 * (kk + 1));
            }
            const u64* bAp = (const u64*)&bA;
            const u64* bBp = (const u64*)&bB;
            u64 b0 = bAp[0], b1 = bAp[1], b2 = bBp[0], b3 = bBp[1];
#pragma unroll
            for (int i = 0; i < 8; i++) {
                const float* af = (const float*)&a[i];
                float av = af[j];
                u64 a2 = pack2(av, av);
                c[i][0] = fma2(a2, b0, c[i][0]);
                c[i][1] = fma2(a2, b1, c[i][1]);
                c[i][2] = fma2(a2, b2, c[i][2]);
                c[i][3] = fma2(a2, b3, c[i][3]);
            }
            bA = nA; bB = nB;
            if (j == 3) {
#pragma unroll
                for (int i = 0; i < 8; i++) a[i] = an[i];
            }
        }
    }
}

// relu(c + bias) -> dst (dst pre-offset by cb; rows rg+16i; 8 consecutive cols)
static __device__ __forceinline__ void store_relu_bias(float* __restrict__ dst,
                                                       int rg,
                                                       const u64 c[8][4],
                                                       float4 biasA, float4 biasB) {
#pragma unroll
    for (int i = 0; i < 8; i++) {
        float* drow = dst + (rg + 16 * i) * LDH;
        float2 v0 = unpack2(c[i][0]);
        float2 v1 = unpack2(c[i][1]);
        float4 o;
        o.x = fmaxf(v0.x + biasA.x, 0.0f);
        o.y = fmaxf(v0.y + biasA.y, 0.0f);
        o.z = fmaxf(v1.x + biasA.z, 0.0f);
        o.w = fmaxf(v1.y + biasA.w, 0.0f);
        *(float4*)(drow) = o;
        float2 w0 = unpack2(c[i][2]);
        float2 w1 = unpack2(c[i][3]);
        float4 q;
        q.x = fmaxf(w0.x + biasB.x, 0.0f);
        q.y = fmaxf(w0.y + biasB.y, 0.0f);
        q.z = fmaxf(w1.x + biasB.z, 0.0f);
        q.w = fmaxf(w1.y + biasB.w, 0.0f);
        *(float4*)(drow + 4) = q;
    }
}

static __device__ __forceinline__ void store_relu(float* __restrict__ dst,
                                                  int rg,
                                                  const u64 c[8][4]) {
#pragma unroll
    for (int i = 0; i < 8; i++) {
        float* drow = dst + (rg + 16 * i) * LDH;
        float2 v0 = unpack2(c[i][0]);
        float2 v1 = unpack2(c[i][1]);
        float4 o;
        o.x = fmaxf(v0.x, 0.0f); o.y = fmaxf(v0.y, 0.0f);
        o.z = fmaxf(v1.x, 0.0f); o.w = fmaxf(v1.y, 0.0f);
        *(float4*)(drow) = o;
        float2 w0 = unpack2(c[i][2]);
        float2 w1 = unpack2(c[i][3]);
        float4 q;
        q.x = fmaxf(w0.x, 0.0f); q.y = fmaxf(w0.y, 0.0f);
        q.z = fmaxf(w1.x, 0.0f); q.w = fmaxf(w1.y, 0.0f);
        *(float4*)(drow + 4) = q;
    }
}

__global__ void __launch_bounds__(NTHREADS, 1)
sde_rollout_kernel(const float* __restrict__ X0, const float* __restrict__ V0,
                   const float* __restrict__ obs, const float* __restrict__ noise,
                   const float* __restrict__ W1, const float* __restrict__ b1,
                   const float* __restrict__ W2, const float* __restrict__ b2,
                   const float* __restrict__ W3, const float* __restrict__ b3,
                   float* __restrict__ out) {
    extern __shared__ float sm[];
    float* W1xs = sm;                       // 16*128 = 2048  (W1 rows 1..16: X part)
    float* w1ts = W1xs + 16 * HDIM;         // 128            (W1 row 0: t part)
    float* b1s  = w1ts + HDIM;              // 128
    float* W2s  = b1s + HDIM;               // 128*128 = 16384
    float* b2s  = W2s + HDIM * HDIM;        // 128
    float* W3s  = b2s + HDIM;               // 128*16 = 2048
    float* b3s  = W3s + HDIM * DDIM;        // 16
    float* sIn  = b3s + 16;                 // 128*16 = 2048  (X state)
    float* sH   = sIn + BLK_P * LDIN;       // 128*132 = 16896
    float* sV   = sH + BLK_P * LDH;         // 128
    float* base = sV + BLK_P;               // 128*132 = 16896 (obs@W1o + b1)
    // total = 56848 floats = 227392 B

    const int tid = threadIdx.x;
    const int pbase = blockIdx.x * BLK_P;

    // ---- cooperative weight load ----
    for (int i = tid; i < (16 * HDIM) / 4; i += NTHREADS)
        ((float4*)W1xs)[i] = ((const float4*)(W1 + HDIM))[i];       // rows 1..16
    for (int i = tid; i < (HDIM * HDIM) / 4; i += NTHREADS)
        ((float4*)W2s)[i] = ((const float4*)W2)[i];
    for (int i = tid; i < (HDIM * DDIM) / 4; i += NTHREADS)
        ((float4*)W3s)[i] = ((const float4*)W3)[i];
    if (tid < HDIM) {
        w1ts[tid] = W1[tid];                                        // row 0
        b1s[tid] = b1[tid];
        b2s[tid] = b2[tid];
    }
    if (tid < DDIM) b3s[tid] = b3[tid];
    // W1 obs rows (17..24) -> scratch: base rows 0..7
    for (int s = tid; s < PDIM * HDIM; s += NTHREADS) {
        int k = s >> 7, cc = s & 127;
        base[k * LDH + cc] = W1[(17 + k) * HDIM + cc];
    }

    // ---- init particle state (2 threads per particle, 8 dims each) ----
    const int p  = tid >> 1;
    const int dh = (tid & 1) * 8;
    const int pg = pbase + p;
    {
        float4 xa = *(const float4*)(X0 + (size_t)pg * DDIM + dh);
        float4 xb = *(const float4*)(X0 + (size_t)pg * DDIM + dh + 4);
        *(float4*)(sIn + p * LDIN + dh)     = xa;
        *(float4*)(sIn + p * LDIN + dh + 4) = xb;
        if ((tid & 1) == 0) {
            sV[p] = V0[pg];
#pragma unroll
            for (int j = 0; j < PDIM; j++)
                sH[p * LDH + j] = obs[(size_t)pg * PDIM + j];       // obs scratch
        }
    }
    __syncthreads();

    // ---- GEMM thread mapping: warp owns a 16-col slice ----
    const int wid  = tid >> 5;          // 0..7  -> cols [16*wid, 16*wid+16)
    const int lane = tid & 31;
    const int rg   = lane >> 1;         // 0..15 -> rows {rg + 16*i}
    const int cb   = wid * 16 + (lane & 1) * 8;   // 8 consecutive cols

    // ---- base = obs @ W1o + b1 (one-time K=8 GEMM) ----
    {
        float acc[8][8];
#pragma unroll
        for (int i = 0; i < 8; i++)
#pragma unroll
            for (int j = 0; j < 8; j++) acc[i][j] = 0.0f;
        for (int k = 0; k < PDIM; k++) {
            float w[8];
#pragma unroll
            for (int j = 0; j < 8; j++)
                w[j] = base[k * LDH + cb + j];
#pragma unroll
            for (int i = 0; i < 8; i++) {
                float o = sH[(rg + 16 * i) * LDH + k];
#pragma unroll
                for (int j = 0; j < 8; j++)
                    acc[i][j] = fmaf(o, w[j], acc[i][j]);
            }
        }
        __syncthreads();    // all W1o reads done before base is overwritten
        float4 c0 = *(const float4*)(b1s + cb);
        float4 c1 = *(const float4*)(b1s + cb + 4);
#pragma unroll
        for (int i = 0; i < 8; i++) {
            int row = rg + 16 * i;
            float4 o0 = { acc[i][0] + c0.x, acc[i][1] + c0.y,
                          acc[i][2] + c0.z, acc[i][3] + c0.w };
            float4 o1 = { acc[i][4] + c1.x, acc[i][5] + c1.y,
                          acc[i][6] + c1.z, acc[i][7] + c1.w };
            *(float4*)(base + row * LDH + cb) = o0;
            *(float4*)(base + row * LDH + cb + 4) = o1;
        }
    }
    __syncthreads();

    const float dt   = (float)(1.0 / (double)M_STEPS);  // T = 1
    const float sqdt = sqrtf(dt);

    // loop-invariant fragments -> registers
    const float4 b2A = *(const float4*)(b2s + cb);
    const float4 b2B = *(const float4*)(b2s + cb + 4);
    const float4 b3a = *(const float4*)(b3s + dh);
    const float4 b3b = *(const float4*)(b3s + dh + 4);
    const float4 w1A = *(const float4*)(w1ts + cb);
    const float4 w1B = *(const float4*)(w1ts + cb + 4);

    for (int m = 0; m < M_STEPS; m++) {
        const float t = (float)m * dt;
        float tw[8] = { t * w1A.x, t * w1A.y, t * w1A.z, t * w1A.w,
                        t * w1B.x, t * w1B.y, t * w1B.z, t * w1B.w };

        // ---- layer 1: h1 = relu(X@W1x + t*W1t + base), K=16 ----
        u64 c[8][4];
#pragma unroll
        for (int i = 0; i < 8; i++) {
            const float* brow = base + (rg + 16 * i) * LDH + cb;
            float4 fA = *(const float4*)(brow);
            float4 fB = *(const float4*)(brow + 4);
            c[i][0] = pack2(fA.x + tw[0], fA.y + tw[1]);
            c[i][1] = pack2(fA.z + tw[2], fA.w + tw[3]);
            c[i][2] = pack2(fB.x + tw[4], fB.y + tw[5]);
            c[i][3] = pack2(fB.z + tw[6], fB.w + tw[7]);
        }
        mm_tile_v<4, LDIN, HDIM>(sIn + rg * LDIN, W1xs + cb, c);
        store_relu(sH + cb, rg, c);
        __syncthreads();

        // ---- layer 2: h2 = relu(h1 @ W2 + b2) ----
#pragma unroll
        for (int i = 0; i < 8; i++) { c[i][0]=0; c[i][1]=0; c[i][2]=0; c[i][3]=0; }
        mm_tile_v<HDIM / 4, LDH, HDIM>(sH + rg * LDH, W2s + cb, c);

        // prefetch this step's noise (hides behind syncs + layer 3)
        const float* np = noise + (((size_t)m * N_PART + pg) * DDIM + dh);
        float4 e0 = *(const float4*)np;
        float4 e1 = *(const float4*)(np + 4);

        __syncthreads();                            // everyone done reading h1
        store_relu_bias(sH + cb, rg, c, b2A, b2B);
        __syncthreads();

        // ---- layer 3: Z = h2 @ W3 + b3 (2 threads/particle, 8 dims each) ----
        u64 cz[4] = {0, 0, 0, 0};
        const float* hrow = sH + p * LDH;
#pragma unroll 4
        for (int kk = 0; kk < HDIM / 4; kk++) {
            float4 hv = *(const float4*)(hrow + 4 * kk);
            const float* hf = (const float*)&hv;
#pragma unroll
            for (int j = 0; j < 4; j++) {
                const int k = 4 * kk + j;
                u64 a2 = pack2(hf[j], hf[j]);
                ulonglong2 w01 = *(const ulonglong2*)(W3s + k * DDIM + dh);
                ulonglong2 w23 = *(const ulonglong2*)(W3s + k * DDIM + dh + 4);
                cz[0] = fma2(a2, w01.x, cz[0]);
                cz[1] = fma2(a2, w01.y, cz[1]);
                cz[2] = fma2(a2, w23.x, cz[2]);
                cz[3] = fma2(a2, w23.y, cz[3]);
            }
        }
        const float* b3f = (const float*)&b3a;
        const float* b3g = (const float*)&b3b;
        float z[8];
        {
            float2 v0 = unpack2(cz[0]), v1 = unpack2(cz[1]);
            float2 v2 = unpack2(cz[2]), v3 = unpack2(cz[3]);
            z[0] = v0.x + b3f[0]; z[1] = v0.y + b3f[1];
            z[2] = v1.x + b3f[2]; z[3] = v1.y + b3f[3];
            z[4] = v2.x + b3g[0]; z[5] = v2.y + b3g[1];
            z[6] = v3.x + b3g[2]; z[7] = v3.y + b3g[3];
        }
        float eps[8] = {e0.x, e0.y, e0.z, e0.w, e1.x, e1.y, e1.z, e1.w};

        float zz = 0.0f, zw = 0.0f;
#pragma unroll
        for (int j = 0; j < 8; j++) {
            zz = fmaf(z[j], z[j], zz);
            zw = fmaf(z[j], sqdt * eps[j], zw);
        }
        zz += __shfl_xor_sync(0xffffffffu, zz, 1);
        zw += __shfl_xor_sync(0xffffffffu, zw, 1);

        // X <- X*(1-dt) + sqrt(dt)*eps   (sigma = 1)
        float* xr = sIn + p * LDIN + dh;
        float4 xv0 = *(const float4*)xr;
        float4 xv1 = *(const float4*)(xr + 4);
        xv0.x = fmaf(xv0.x, 1.0f - dt, sqdt * eps[0]);
        xv0.y = fmaf(xv0.y, 1.0f - dt, sqdt * eps[1]);
        xv0.z = fmaf(xv0.z, 1.0f - dt, sqdt * eps[2]);
        xv0.w = fmaf(xv0.w, 1.0f - dt, sqdt * eps[3]);
        xv1.x = fmaf(xv1.x, 1.0f - dt, sqdt * eps[4]);
        xv1.y = fmaf(xv1.y, 1.0f - dt, sqdt * eps[5]);
        xv1.z = fmaf(xv1.z, 1.0f - dt, sqdt * eps[6]);
        xv1.w = fmaf(xv1.w, 1.0f - dt, sqdt * eps[7]);
        *(float4*)xr = xv0;
        *(float4*)(xr + 4) = xv1;

        if ((tid & 1) == 0)
            sV[p] = sV[p] + dt * 0.5f * zz + zw;     // V update
        __syncthreads();
    }

    // ---- write outputs: X (N*16) then V (N) ----
    {
        float* xo = out + (size_t)pg * DDIM + dh;
        const float* xr = sIn + p * LDIN + dh;
        *(float4*)xo = *(const float4*)xr;
        *(float4*)(xo + 4) = *(const float4*)(xr + 4);
        if ((tid & 1) == 0) out[(size_t)N_PART * DDIM + pg] = sV[p];
    }
}

extern "C" void kernel_launch(void* const* d_in, const int* in_sizes, int n_in,
                              void* d_out, int out_size) {
    const float* X0    = (const float*)d_in[0];
    const float* V0    = (const float*)d_in[1];
    const float* obs   = (const float*)d_in[2];
    const float* noise = (const float*)d_in[3];
    const float* W1    = (const float*)d_in[4];
    const float* b1    = (const float*)d_in[5];
    const float* W2    = (const float*)d_in[6];
    const float* b2    = (const float*)d_in[7];
    const float* W3    = (const float*)d_in[8];
    const float* b3    = (const float*)d_in[9];
    float* out = (float*)d_out;

    const size_t smem_bytes = (size_t)56848 * sizeof(float);   // 227392 B

    cudaFuncSetAttribute(sde_rollout_kernel,
                         cudaFuncAttributeMaxDynamicSharedMemorySize,
                         (int)smem_bytes);

    sde_rollout_kernel<<<N_PART / BLK_P, NTHREADS, smem_bytes>>>(
        X0, V0, obs, noise, W1, b1, W2, b2, W3, b3, out);
}

// round 14
// speedup vs baseline: 1.3124x; 1.1875x over previous
#include <cuda_runtime.h>
#include <math.h>

#define N_PART   16384
#define DDIM     16
#define PDIM     8
#define M_STEPS  50
#define HDIM     128
#define PPC      111       // particles per CTA (148 CTAs cover 16384)
#define BLK_R    112       // padded row count = 7 row-groups of 16
#define NROW     7         // row-groups per thread tile
#define NTHREADS 256
#define LDIN     16        // sIn row stride (X only)
#define LDH      132       // sH / base row stride (132 mod 32 = 4 -> conflict-free)

typedef unsigned long long u64;

static __device__ __forceinline__ u64 pack2(float x, float y) {
    u64 r;
    asm("mov.b64 %0, {%1, %2};" : "=l"(r) : "f"(x), "f"(y));
    return r;
}
static __device__ __forceinline__ u64 fma2(u64 a, u64 b, u64 c) {
    u64 d;
    asm("fma.rn.f32x2 %0, %1, %2, %3;" : "=l"(d) : "l"(a), "l"(b), "l"(c));
    return d;
}
static __device__ __forceinline__ float2 unpack2(u64 v) {
    float2 f;
    asm("mov.b64 {%0, %1}, %2;" : "=f"(f.x), "=f"(f.y) : "l"(v));
    return f;
}

// C tile: NROW rows (ty + 16*i) x 8 cols ({4tx..4tx+3} U {64+4tx..64+4tx+3}).
// A rows at stride 16*LDA, k-chunks of 4 read as float4.
// B: per k, two float4 at [k*LDB+4tx] and [k*LDB+64+4tx]; prefetch 1 k ahead.
// Over-reads one B row / one A chunk past the end (stays inside smem).
template <int K4, int LDA, int LDB>
static __device__ __forceinline__ void mm_tile_v(const float* __restrict__ A,
                                                 const float* __restrict__ B,
                                                 u64 c[NROW][4]) {
    float4 a[NROW];
#pragma unroll
    for (int i = 0; i < NROW; i++)
        a[i] = *(const float4*)(A + i * 16 * LDA);
    float4 bA = *(const float4*)(B);
    float4 bB = *(const float4*)(B + 64);

#pragma unroll 2
    for (int kk = 0; kk < K4; kk++) {
#pragma unroll
        for (int j = 0; j < 4; j++) {
            const int k = 4 * kk + j;
            float4 nA = *(const float4*)(B + (size_t)(k + 1) * LDB);
            float4 nB = *(const float4*)(B + (size_t)(k + 1) * LDB + 64);
            float4 an[NROW];
            if (j == 3) {
#pragma unroll
                for (int i = 0; i < NROW; i++)
                    an[i] = *(const float4*)(A + i * 16 * LDA + 4 * (kk + 1));
            }
            const u64* bAp = (const u64*)&bA;
            const u64* bBp = (const u64*)&bB;
            u64 b0 = bAp[0], b1 = bAp[1], b2 = bBp[0], b3 = bBp[1];
#pragma unroll
            for (int i = 0; i < NROW; i++) {
                const float* af = (const float*)&a[i];
                float av = af[j];
                u64 a2 = pack2(av, av);
                c[i][0] = fma2(a2, b0, c[i][0]);
                c[i][1] = fma2(a2, b1, c[i][1]);
                c[i][2] = fma2(a2, b2, c[i][2]);
                c[i][3] = fma2(a2, b3, c[i][3]);
            }
            bA = nA; bB = nB;
            if (j == 3) {
#pragma unroll
                for (int i = 0; i < NROW; i++) a[i] = an[i];
            }
        }
    }
}

static __device__ __forceinline__ void store_relu_bias(float* __restrict__ dst,
                                                       int ty, int tx,
                                                       const u64 c[NROW][4],
                                                       float4 biasA, float4 biasB) {
#pragma unroll
    for (int i = 0; i < NROW; i++) {
        float* drow = dst + (ty + 16 * i) * LDH;
        float2 v0 = unpack2(c[i][0]);
        float2 v1 = unpack2(c[i][1]);
        float4 o;
        o.x = fmaxf(v0.x + biasA.x, 0.0f);
        o.y = fmaxf(v0.y + biasA.y, 0.0f);
        o.z = fmaxf(v1.x + biasA.z, 0.0f);
        o.w = fmaxf(v1.y + biasA.w, 0.0f);
        *(float4*)(drow + 4 * tx) = o;
        float2 w0 = unpack2(c[i][2]);
        float2 w1 = unpack2(c[i][3]);
        float4 q;
        q.x = fmaxf(w0.x + biasB.x, 0.0f);
        q.y = fmaxf(w0.y + biasB.y, 0.0f);
        q.z = fmaxf(w1.x + biasB.z, 0.0f);
        q.w = fmaxf(w1.y + biasB.w, 0.0f);
        *(float4*)(drow + 64 + 4 * tx) = q;
    }
}

static __device__ __forceinline__ void store_relu(float* __restrict__ dst,
                                                  int ty, int tx,
                                                  const u64 c[NROW][4]) {
#pragma unroll
    for (int i = 0; i < NROW; i++) {
        float* drow = dst + (ty + 16 * i) * LDH;
        float2 v0 = unpack2(c[i][0]);
        float2 v1 = unpack2(c[i][1]);
        float4 o;
        o.x = fmaxf(v0.x, 0.0f); o.y = fmaxf(v0.y, 0.0f);
        o.z = fmaxf(v1.x, 0.0f); o.w = fmaxf(v1.y, 0.0f);
        *(float4*)(drow + 4 * tx) = o;
        float2 w0 = unpack2(c[i][2]);
        float2 w1 = unpack2(c[i][3]);
        float4 q;
        q.x = fmaxf(w0.x, 0.0f); q.y = fmaxf(w0.y, 0.0f);
        q.z = fmaxf(w1.x, 0.0f); q.w = fmaxf(w1.y, 0.0f);
        *(float4*)(drow + 64 + 4 * tx) = q;
    }
}

__global__ void __launch_bounds__(NTHREADS, 1)
sde_rollout_kernel(const float* __restrict__ X0, const float* __restrict__ V0,
                   const float* __restrict__ obs, const float* __restrict__ noise,
                   const float* __restrict__ W1, const float* __restrict__ b1,
                   const float* __restrict__ W2, const float* __restrict__ b2,
                   const float* __restrict__ W3, const float* __restrict__ b3,
                   float* __restrict__ out) {
    extern __shared__ float sm[];
    float* W1xs = sm;                       // 16*128 = 2048  (W1 rows 1..16: X part)
    float* w1ts = W1xs + 16 * HDIM;         // 128            (W1 row 0: t part)
    float* b1s  = w1ts + HDIM;              // 128
    float* W2s  = b1s + HDIM;               // 128*128 = 16384
    float* b2s  = W2s + HDIM * HDIM;        // 128
    float* W3s  = b2s + HDIM;               // 128*16 = 2048
    float* b3s  = W3s + HDIM * DDIM;        // 16
    float* sIn  = b3s + 16;                 // 128*16 = 2048  (X state, rows 0..111 used)
    float* sH   = sIn + 128 * LDIN;         // 128*132 = 16896
    float* sV   = sH + 128 * LDH;           // 128
    float* base = sV + 128;                 // 128*132 = 16896 (obs@W1o + b1)
    // total = 56848 floats = 227392 B

    const int tid = threadIdx.x;
    const int pbase = blockIdx.x * PPC;
    const int count = min(PPC, N_PART - pbase);     // real particles in this CTA

    // ---- cooperative weight load ----
    for (int i = tid; i < (16 * HDIM) / 4; i += NTHREADS)
        ((float4*)W1xs)[i] = ((const float4*)(W1 + HDIM))[i];       // rows 1..16
    for (int i = tid; i < (HDIM * HDIM) / 4; i += NTHREADS)
        ((float4*)W2s)[i] = ((const float4*)W2)[i];
    for (int i = tid; i < (HDIM * DDIM) / 4; i += NTHREADS)
        ((float4*)W3s)[i] = ((const float4*)W3)[i];
    if (tid < HDIM) {
        w1ts[tid] = W1[tid];                                        // row 0
        b1s[tid] = b1[tid];
        b2s[tid] = b2[tid];
    }
    if (tid < DDIM) b3s[tid] = b3[tid];
    // W1 obs rows (17..24) -> scratch: base rows 0..7
    for (int s = tid; s < PDIM * HDIM; s += NTHREADS) {
        int k = s >> 7, cc = s & 127;
        base[k * LDH + cc] = W1[(17 + k) * HDIM + cc];
    }

    // ---- init particle state (2 threads per particle, 8 dims each) ----
    const int p  = tid >> 1;            // 0..127 (rows >= BLK_R unused)
    const int dh = (tid & 1) * 8;
    const int pg = pbase + p;
    const int pgc = pg < N_PART ? pg : N_PART - 1;   // clamped for loads
    if (p < BLK_R) {
        float4 xa, xb;
        if (p < count) {
            xa = *(const float4*)(X0 + (size_t)pg * DDIM + dh);
            xb = *(const float4*)(X0 + (size_t)pg * DDIM + dh + 4);
        } else {
            xa = make_float4(0.f, 0.f, 0.f, 0.f);
            xb = xa;
        }
        *(float4*)(sIn + p * LDIN + dh)     = xa;
        *(float4*)(sIn + p * LDIN + dh + 4) = xb;
        if ((tid & 1) == 0) {
            sV[p] = (p < count) ? V0[pg] : 0.0f;
#pragma unroll
            for (int j = 0; j < PDIM; j++)
                sH[p * LDH + j] = (p < count) ? obs[(size_t)pg * PDIM + j] : 0.0f;
        }
    }
    __syncthreads();

    const int ty = tid >> 4, tx = tid & 15;

    // ---- base = obs @ W1o + b1 (one-time K=8 GEMM) ----
    {
        float acc[NROW][8];
#pragma unroll
        for (int i = 0; i < NROW; i++)
#pragma unroll
            for (int j = 0; j < 8; j++) acc[i][j] = 0.0f;
        for (int k = 0; k < PDIM; k++) {
            float w[8];
#pragma unroll
            for (int j = 0; j < 4; j++) {
                w[j]     = base[k * LDH + 4 * tx + j];
                w[4 + j] = base[k * LDH + 64 + 4 * tx + j];
            }
#pragma unroll
            for (int i = 0; i < NROW; i++) {
                float o = sH[(ty + 16 * i) * LDH + k];
#pragma unroll
                for (int j = 0; j < 8; j++)
                    acc[i][j] = fmaf(o, w[j], acc[i][j]);
            }
        }
        __syncthreads();    // all W1o reads done before base is overwritten
        float4 c0 = *(const float4*)(b1s + 4 * tx);
        float4 c1 = *(const float4*)(b1s + 64 + 4 * tx);
#pragma unroll
        for (int i = 0; i < NROW; i++) {
            int row = ty + 16 * i;
            float4 o0 = { acc[i][0] + c0.x, acc[i][1] + c0.y,
                          acc[i][2] + c0.z, acc[i][3] + c0.w };
            float4 o1 = { acc[i][4] + c1.x, acc[i][5] + c1.y,
                          acc[i][6] + c1.z, acc[i][7] + c1.w };
            *(float4*)(base + row * LDH + 4 * tx) = o0;
            *(float4*)(base + row * LDH + 64 + 4 * tx) = o1;
        }
    }
    __syncthreads();

    const float dt   = (float)(1.0 / (double)M_STEPS);  // T = 1
    const float sqdt = sqrtf(dt);

    // loop-invariant fragments -> registers
    const float4 b2A = *(const float4*)(b2s + 4 * tx);
    const float4 b2B = *(const float4*)(b2s + 64 + 4 * tx);
    const float4 b3a = *(const float4*)(b3s + dh);
    const float4 b3b = *(const float4*)(b3s + dh + 4);
    const float4 w1A = *(const float4*)(w1ts + 4 * tx);
    const float4 w1B = *(const float4*)(w1ts + 64 + 4 * tx);

    for (int m = 0; m < M_STEPS; m++) {
        const float t = (float)m * dt;
        float tw[8] = { t * w1A.x, t * w1A.y, t * w1A.z, t * w1A.w,
                        t * w1B.x, t * w1B.y, t * w1B.z, t * w1B.w };

        // ---- layer 1: h1 = relu(X@W1x + t*W1t + base), K=16 ----
        u64 c[NROW][4];
#pragma unroll
        for (int i = 0; i < NROW; i++) {
            const float* brow = base + (ty + 16 * i) * LDH;
            float4 fA = *(const float4*)(brow + 4 * tx);
            float4 fB = *(const float4*)(brow + 64 + 4 * tx);
            c[i][0] = pack2(fA.x + tw[0], fA.y + tw[1]);
            c[i][1] = pack2(fA.z + tw[2], fA.w + tw[3]);
            c[i][2] = pack2(fB.x + tw[4], fB.y + tw[5]);
            c[i][3] = pack2(fB.z + tw[6], fB.w + tw[7]);
        }
        mm_tile_v<4, LDIN, HDIM>(sIn + ty * LDIN, W1xs + 4 * tx, c);
        store_relu(sH, ty, tx, c);
        __syncthreads();

        // ---- layer 2: h2 = relu(h1 @ W2 + b2) ----
#pragma unroll
        for (int i = 0; i < NROW; i++) { c[i][0]=0; c[i][1]=0; c[i][2]=0; c[i][3]=0; }
        mm_tile_v<HDIM / 4, LDH, HDIM>(sH + ty * LDH, W2s + 4 * tx, c);

        // prefetch this step's noise (hides behind syncs + layer 3)
        float4 e0, e1;
        if (p < BLK_R) {
            const float* np = noise + (((size_t)m * N_PART + pgc) * DDIM + dh);
            e0 = *(const float4*)np;
            e1 = *(const float4*)(np + 4);
        }

        __syncthreads();                            // everyone done reading h1
        store_relu_bias(sH, ty, tx, c, b2A, b2B);
        __syncthreads();

        if (p < BLK_R) {   // warps 0..6 only (tid < 224)
            // ---- layer 3: Z = h2 @ W3 + b3 (2 threads/particle, 8 dims each) ----
            u64 cz[4] = {0, 0, 0, 0};
            const float* hrow = sH + p * LDH;
#pragma unroll 4
            for (int kk = 0; kk < HDIM / 4; kk++) {
                float4 hv = *(const float4*)(hrow + 4 * kk);
                const float* hf = (const float*)&hv;
#pragma unroll
                for (int j = 0; j < 4; j++) {
                    const int k = 4 * kk + j;
                    u64 a2 = pack2(hf[j], hf[j]);
                    ulonglong2 w01 = *(const ulonglong2*)(W3s + k * DDIM + dh);
                    ulonglong2 w23 = *(const ulonglong2*)(W3s + k * DDIM + dh + 4);
                    cz[0] = fma2(a2, w01.x, cz[0]);
                    cz[1] = fma2(a2, w01.y, cz[1]);
                    cz[2] = fma2(a2, w23.x, cz[2]);
                    cz[3] = fma2(a2, w23.y, cz[3]);
                }
            }
            const float* b3f = (const float*)&b3a;
            const float* b3g = (const float*)&b3b;
            float z[8];
            {
                float2 v0 = unpack2(cz[0]), v1 = unpack2(cz[1]);
                float2 v2 = unpack2(cz[2]), v3 = unpack2(cz[3]);
                z[0] = v0.x + b3f[0]; z[1] = v0.y + b3f[1];
                z[2] = v1.x + b3f[2]; z[3] = v1.y + b3f[3];
                z[4] = v2.x + b3g[0]; z[5] = v2.y + b3g[1];
                z[6] = v3.x + b3g[2]; z[7] = v3.y + b3g[3];
            }
            float eps[8] = {e0.x, e0.y, e0.z, e0.w, e1.x, e1.y, e1.z, e1.w};

            float zz = 0.0f, zw = 0.0f;
#pragma unroll
            for (int j = 0; j < 8; j++) {
                zz = fmaf(z[j], z[j], zz);
                zw = fmaf(z[j], sqdt * eps[j], zw);
            }
            zz += __shfl_xor_sync(0xffffffffu, zz, 1);
            zw += __shfl_xor_sync(0xffffffffu, zw, 1);

            // X <- X*(1-dt) + sqrt(dt)*eps   (sigma = 1)
            float* xr = sIn + p * LDIN + dh;
            float4 xv0 = *(const float4*)xr;
            float4 xv1 = *(const float4*)(xr + 4);
            xv0.x = fmaf(xv0.x, 1.0f - dt, sqdt * eps[0]);
            xv0.y = fmaf(xv0.y, 1.0f - dt, sqdt * eps[1]);
            xv0.z = fmaf(xv0.z, 1.0f - dt, sqdt * eps[2]);
            xv0.w = fmaf(xv0.w, 1.0f - dt, sqdt * eps[3]);
            xv1.x = fmaf(xv1.x, 1.0f - dt, sqdt * eps[4]);
            xv1.y = fmaf(xv1.y, 1.0f - dt, sqdt * eps[5]);
            xv1.z = fmaf(xv1.z, 1.0f - dt, sqdt * eps[6]);
            xv1.w = fmaf(xv1.w, 1.0f - dt, sqdt * eps[7]);
            *(float4*)xr = xv0;
            *(float4*)(xr + 4) = xv1;

            if ((tid & 1) == 0)
                sV[p] = sV[p] + dt * 0.5f * zz + zw;     // V update
        }
        __syncthreads();
    }

    // ---- write outputs: X (N*16) then V (N), real particles only ----
    if (p < count) {
        float* xo = out + (size_t)pg * DDIM + dh;
        const float* xr = sIn + p * LDIN + dh;
        *(float4*)xo = *(const float4*)xr;
        *(float4*)(xo + 4) = *(const float4*)(xr + 4);
        if ((tid & 1) == 0) out[(size_t)N_PART * DDIM + pg] = sV[p];
    }
}

extern "C" void kernel_launch(void* const* d_in, const int* in_sizes, int n_in,
                              void* d_out, int out_size) {
    const float* X0    = (const float*)d_in[0];
    const float* V0    = (const float*)d_in[1];
    const float* obs   = (const float*)d_in[2];
    const float* noise = (const float*)d_in[3];
    const float* W1    = (const float*)d_in[4];
    const float* b1    = (const float*)d_in[5];
    const float* W2    = (const float*)d_in[6];
    const float* b2    = (const float*)d_in[7];
    const float* W3    = (const float*)d_in[8];
    const float* b3    = (const float*)d_in[9];
    float* out = (float*)d_out;

    const size_t smem_bytes = (size_t)56848 * sizeof(float);   // 227392 B

    cudaFuncSetAttribute(sde_rollout_kernel,
                         cudaFuncAttributeMaxDynamicSharedMemorySize,
                         (int)smem_bytes);

    const int grid = (N_PART + PPC - 1) / PPC;   // 148
    sde_rollout_kernel<<<grid, NTHREADS, smem_bytes>>>(
        X0, V0, obs, noise, W1, b1, W2, b2, W3, b3, out);
}